// round 13
// baseline (speedup 1.0000x reference)
#include <cuda_runtime.h>
#include <cuda_fp16.h>
#include <cstdint>

#define TT    128
#define BM    28          // valid batches per CTA (padded to 32 in the GEMM)
#define NTHR  256
#define PW    52          // 32-bit words per state row (k 0..95 fp16 + pad)
#define PH    65          // final-h pitch (floats)

#define STB       (32*PW)               // words per state buffer
#define BIAS_F    (2*STB)
#define HFIN_F    (BIAS_F + 256)
#define SMEM_FLOATS (HFIN_F + 32*PH)
#define SMEM_BYTES  (SMEM_FLOATS*4)

__device__ __forceinline__ uint32_t packh2(float lo, float hi) {
    __half2 p = __halves2half2(__float2half_rn(lo), __float2half_rn(hi));
    return *reinterpret_cast<uint32_t*>(&p);
}
__device__ __forceinline__ uint32_t f2h2(float lo, float hi) {
    __half2 p = __floats2half2_rn(lo, hi);          // .x = lo, .y = hi
    return *reinterpret_cast<uint32_t*>(&p);
}
__device__ __forceinline__ float2 h22f2(uint32_t u) {
    __half2 p = *reinterpret_cast<__half2*>(&u);
    return __half22float2(p);                       // .x = lo, .y = hi
}
__device__ __forceinline__ uint32_t tanh2(uint32_t v) {
    uint32_t r; asm("tanh.approx.f16x2 %0, %1;" : "=r"(r) : "r"(v)); return r;
}

__device__ __forceinline__ void mma16(float d[4], const uint32_t a[4],
                                      uint32_t b0, uint32_t b1) {
    asm volatile(
        "mma.sync.aligned.m16n8k16.row.col.f32.f16.f16.f32 "
        "{%0,%1,%2,%3}, {%4,%5,%6,%7}, {%8,%9}, {%0,%1,%2,%3};"
        : "+f"(d[0]), "+f"(d[1]), "+f"(d[2]), "+f"(d[3])
        : "r"(a[0]), "r"(a[1]), "r"(a[2]), "r"(a[3]), "r"(b0), "r"(b1));
}

// raw weight element: gate g, unit u, feature k (k<32: W_ih, else W_hh)
__device__ __forceinline__ float wval(const float* __restrict__ W_ih,
                                      const float* __restrict__ W_hh,
                                      int g, int u, int k) {
    return (k < 32) ? W_ih[(g * 64 + u) * 32 + k]
                    : W_hh[(g * 64 + u) * 64 + (k - 32)];
}

__global__ void __launch_bounds__(NTHR, 2)
lstm_mma(const float* __restrict__ x,
         const float* __restrict__ W_ih,
         const float* __restrict__ W_hh,
         const float* __restrict__ b_ih,
         const float* __restrict__ b_hh,
         const float* __restrict__ W_fc,
         const float* __restrict__ b_fc,
         float* __restrict__ out,
         int Btotal)
{
    extern __shared__ float sm[];
    uint32_t* stw = (uint32_t*)sm;       // 2 x state[32][PW]: k 0-31 x, 32-95 h (fp16)
    __half*   sth = (__half*)sm;
    float* bias = sm + BIAS_F;           // bias[u*4+g], gates i/f/o pre-scaled by 0.5
    float* hfin = sm + HFIN_F;           // hfin[batch][unit] raw f32 h(T)

    const int tid   = threadIdx.x;
    const int w     = tid >> 5;          // 0..7
    const int l     = tid & 31;
    const int bbase = blockIdx.x * BM;

    for (int m = tid; m < 256; m += NTHR) {     // m = gate*64+unit
        int u = m & 63, g = m >> 6;
        float s = (g == 2) ? 1.0f : 0.5f;
        bias[u * 4 + g] = s * (b_ih[m] + b_hh[m]);
    }
    for (int i = tid; i < 2 * STB; i += NTHR)
        stw[i] = 0u;

    // ---- warp tile: warp w owns units 8w..8w+7 (32 gate rows), all 32 batch ----
    const int fr = l >> 2;              // 0..7
    const int fc = l & 3;               // 0..3
    const int un = 8 * w + fr;          // this thread's unit

    // persistent A fragments, gate->fragment-row remap:
    // tile0: rows fr -> gate i (x0.5), fr+8 -> gate f (x0.5)
    // tile1: rows fr -> gate g (x1),   fr+8 -> gate o (x0.5)
    uint32_t A[2][6][4];
#pragma unroll
    for (int mt = 0; mt < 2; ++mt) {
        const int ga = 2 * mt, gb = 2 * mt + 1;
        const float sa = (ga == 2) ? 1.0f : 0.5f;
        const float sb = 0.5f;
#pragma unroll
        for (int kt = 0; kt < 6; ++kt) {
            const int k0 = kt * 16 + fc * 2;
            A[mt][kt][0] = packh2(sa * wval(W_ih, W_hh, ga, un, k0),
                                  sa * wval(W_ih, W_hh, ga, un, k0 + 1));
            A[mt][kt][1] = packh2(sb * wval(W_ih, W_hh, gb, un, k0),
                                  sb * wval(W_ih, W_hh, gb, un, k0 + 1));
            A[mt][kt][2] = packh2(sa * wval(W_ih, W_hh, ga, un, k0 + 8),
                                  sa * wval(W_ih, W_hh, ga, un, k0 + 9));
            A[mt][kt][3] = packh2(sb * wval(W_ih, W_hh, gb, un, k0 + 8),
                                  sb * wval(W_ih, W_hh, gb, un, k0 + 9));
        }
    }

    // ---- x staging (224 threads): batch lb (0..27), features iv..iv+3 ----
    const int lb  = tid >> 3;
    const int iv  = (tid & 7) * 4;
    const bool xth  = (tid < 224);
    const bool bval = xth && (bbase + lb) < Btotal;
    const float* xrow = x + (bval ? (size_t)(bbase + lb) * TT * 32 : 0) + iv;

    float4 xr;
    if (xth) {
        float4 x0 = *(const float4*)xrow;
        stw[lb * PW + (iv >> 1)]     = packh2(x0.x, x0.y);      // buf 0
        stw[lb * PW + (iv >> 1) + 1] = packh2(x0.z, x0.w);
        xr = *(const float4*)(xrow + 32);
    }
    __syncthreads();

    const float4 bz = *(const float4*)&bias[un * 4];
    float cst[8];
#pragma unroll
    for (int i = 0; i < 8; ++i) cst[i] = 0.0f;

    int p = 0;
    for (int t = 0; t < TT; ++t) {
        const uint32_t* sb = stw + p * STB;
        const int q = 1 - p;

        // ===== GEMM: all 4 gates of unit `un`, 8 batches, from buf p =====
        float D0[4][4], D1[4][4];
#pragma unroll
        for (int ntp = 0; ntp < 4; ++ntp) {
            const int n0 = 8 * ntp;
            const uint32_t* s0 = sb + (n0 + fr) * PW + fc;
#pragma unroll
            for (int e = 0; e < 4; ++e) { D0[ntp][e] = 0.f; D1[ntp][e] = 0.f; }
#pragma unroll
            for (int kt = 0; kt < 6; ++kt) {
                uint32_t b0 = s0[kt * 8];
                uint32_t b1 = s0[kt * 8 + 4];
                mma16(D0[ntp], A[0][kt], b0, b1);
                mma16(D1[ntp], A[1][kt], b0, b1);
            }
        }

        // stage x(t+1) into buf q early (independent of activations)
        if (xth && t + 1 < TT) {
            stw[q * STB + lb * PW + (iv >> 1)]     = packh2(xr.x, xr.y);
            stw[q * STB + lb * PW + (iv >> 1) + 1] = packh2(xr.z, xr.w);
            int tn = (t + 2 < TT) ? (t + 2) : (TT - 1);
            xr = *(const float4*)(xrow + (size_t)tn * 32);
        }

        // ===== activations: f16x2 tanh on batch pairs; c stays f32 =====
        const bool lastt = (t == TT - 1);
#pragma unroll
        for (int ntp = 0; ntp < 4; ++ntp) {
            // pairs (e=0, e=1): batches b0 = 8ntp+2fc, b1 = b0+1
            float2 ti = h22f2(tanh2(f2h2(D0[ntp][0] + bz.x, D0[ntp][1] + bz.x)));
            float2 tf = h22f2(tanh2(f2h2(D0[ntp][2] + bz.y, D0[ntp][3] + bz.y)));
            float2 tg = h22f2(tanh2(f2h2(D1[ntp][0] + bz.z, D1[ntp][1] + bz.z)));
            float2 to = h22f2(tanh2(f2h2(D1[ntp][2] + bz.w, D1[ntp][3] + bz.w)));
            float gi0 = fmaf(ti.x, 0.5f, 0.5f), gi1 = fmaf(ti.y, 0.5f, 0.5f);
            float gf0 = fmaf(tf.x, 0.5f, 0.5f), gf1 = fmaf(tf.y, 0.5f, 0.5f);
            float go0 = fmaf(to.x, 0.5f, 0.5f), go1 = fmaf(to.y, 0.5f, 0.5f);

            const int ci = 2 * ntp;
            float cn0 = fmaf(gf0, cst[ci],     gi0 * tg.x);
            float cn1 = fmaf(gf1, cst[ci + 1], gi1 * tg.y);
            cst[ci] = cn0; cst[ci + 1] = cn1;
            float2 tc = h22f2(tanh2(f2h2(cn0, cn1)));
            float h0 = go0 * tc.x;
            float h1 = go1 * tc.y;

            const int b0 = 8 * ntp + 2 * fc;
            if (lastt) {
                hfin[b0 * PH + un]       = h0;
                hfin[(b0 + 1) * PH + un] = h1;
            } else {
                sth[q * (2 * STB) + b0 * (2 * PW) + 32 + un]       = __float2half_rn(h0);
                sth[q * (2 * STB) + (b0 + 1) * (2 * PW) + 32 + un] = __float2half_rn(h1);
            }
        }

        __syncthreads();
        p = q;
    }

    // ---- final FC on raw f32 h(T) ----
    if (xth) {
        const int ob = tid >> 3, oo = tid & 7;
        if ((bbase + ob) < Btotal) {
            const float* hv = hfin + ob * PH;
            float a = b_fc[oo];
#pragma unroll 8
            for (int k = 0; k < 64; ++k)
                a = fmaf(hv[k], W_fc[oo * 64 + k], a);
            out[(size_t)(bbase + ob) * 8 + oo] = a;
        }
    }
}

extern "C" void kernel_launch(void* const* d_in, const int* in_sizes, int n_in,
                              void* d_out, int out_size) {
    const float* x    = (const float*)d_in[0];
    const float* W_ih = (const float*)d_in[1];
    const float* W_hh = (const float*)d_in[2];
    const float* b_ih = (const float*)d_in[3];
    const float* b_hh = (const float*)d_in[4];
    const float* W_fc = (const float*)d_in[5];
    const float* b_fc = (const float*)d_in[6];
    float* out = (float*)d_out;

    const int B = in_sizes[0] / (TT * 32);    // 8192
    const int grid = (B + BM - 1) / BM;       // 293

    cudaFuncSetAttribute(lstm_mma,
                         cudaFuncAttributeMaxDynamicSharedMemorySize,
                         SMEM_BYTES);
    lstm_mma<<<grid, NTHR, SMEM_BYTES>>>(x, W_ih, W_hh, b_ih, b_hh,
                                         W_fc, b_fc, out, B);
}

// round 14
// speedup vs baseline: 1.0683x; 1.0683x over previous
#include <cuda_runtime.h>
#include <cuda_fp16.h>
#include <cstdint>

#define TT    128
#define BM    28          // valid batches per CTA (padded to 32 in the GEMM)
#define NTHR  256
#define PW    52          // 32-bit words per state row (k 0..95 fp16 + pad)
#define PH    65          // final-h pitch (floats)

#define STB       (32*PW)               // words per state buffer
#define BIAS_F    (2*STB)
#define HFIN_F    (BIAS_F + 256)
#define SMEM_FLOATS (HFIN_F + 32*PH)
#define SMEM_BYTES  (SMEM_FLOATS*4)

#define SKEW_CYC  1500ull               // ~half a step period

__device__ __forceinline__ uint32_t packh2(float lo, float hi) {
    __half2 p = __halves2half2(__float2half_rn(lo), __float2half_rn(hi));
    return *reinterpret_cast<uint32_t*>(&p);
}

__device__ __forceinline__ void mma16(float d[4], const uint32_t a[4],
                                      uint32_t b0, uint32_t b1) {
    asm volatile(
        "mma.sync.aligned.m16n8k16.row.col.f32.f16.f16.f32 "
        "{%0,%1,%2,%3}, {%4,%5,%6,%7}, {%8,%9}, {%0,%1,%2,%3};"
        : "+f"(d[0]), "+f"(d[1]), "+f"(d[2]), "+f"(d[3])
        : "r"(a[0]), "r"(a[1]), "r"(a[2]), "r"(a[3]), "r"(b0), "r"(b1));
}

__device__ __forceinline__ float tanha(float v) {
    float r; asm("tanh.approx.f32 %0, %1;" : "=f"(r) : "f"(v)); return r;
}
// sigmoid with the 0.5 input scale pre-folded into weights/bias
__device__ __forceinline__ float fsigp(float half_v) {
    return fmaf(tanha(half_v), 0.5f, 0.5f);
}

// raw weight element: gate g, unit u, feature k (k<32: W_ih, else W_hh)
__device__ __forceinline__ float wval(const float* __restrict__ W_ih,
                                      const float* __restrict__ W_hh,
                                      int g, int u, int k) {
    return (k < 32) ? W_ih[(g * 64 + u) * 32 + k]
                    : W_hh[(g * 64 + u) * 64 + (k - 32)];
}

__global__ void __launch_bounds__(NTHR, 2)
lstm_mma(const float* __restrict__ x,
         const float* __restrict__ W_ih,
         const float* __restrict__ W_hh,
         const float* __restrict__ b_ih,
         const float* __restrict__ b_hh,
         const float* __restrict__ W_fc,
         const float* __restrict__ b_fc,
         float* __restrict__ out,
         int Btotal)
{
    extern __shared__ float sm[];
    uint32_t* stw = (uint32_t*)sm;       // 2 x state[32][PW]: k 0-31 x, 32-95 h (fp16)
    __half*   sth = (__half*)sm;
    float* bias = sm + BIAS_F;           // bias[u*4+g], gates i/f/o pre-scaled by 0.5
    float* hfin = sm + HFIN_F;           // hfin[batch][unit] raw f32 h(T)

    const int tid   = threadIdx.x;
    const int w     = tid >> 5;          // 0..7
    const int l     = tid & 31;
    const int bbase = blockIdx.x * BM;

    for (int m = tid; m < 256; m += NTHR) {     // m = gate*64+unit
        int u = m & 63, g = m >> 6;
        float s = (g == 2) ? 1.0f : 0.5f;
        bias[u * 4 + g] = s * (b_ih[m] + b_hh[m]);
    }
    for (int i = tid; i < 2 * STB; i += NTHR)
        stw[i] = 0u;

    // ---- warp tile: warp w owns units 8w..8w+7 (32 gate rows), all 32 batch ----
    const int fr = l >> 2;              // 0..7
    const int fc = l & 3;               // 0..3
    const int un = 8 * w + fr;          // this thread's unit

    // persistent A fragments, gate->fragment-row remap:
    // tile0: rows fr -> gate i (x0.5), fr+8 -> gate f (x0.5)
    // tile1: rows fr -> gate g (x1),   fr+8 -> gate o (x0.5)
    uint32_t A[2][6][4];
#pragma unroll
    for (int mt = 0; mt < 2; ++mt) {
        const int ga = 2 * mt, gb = 2 * mt + 1;
        const float sa = (ga == 2) ? 1.0f : 0.5f;
        const float sb = 0.5f;
#pragma unroll
        for (int kt = 0; kt < 6; ++kt) {
            const int k0 = kt * 16 + fc * 2;
            A[mt][kt][0] = packh2(sa * wval(W_ih, W_hh, ga, un, k0),
                                  sa * wval(W_ih, W_hh, ga, un, k0 + 1));
            A[mt][kt][1] = packh2(sb * wval(W_ih, W_hh, gb, un, k0),
                                  sb * wval(W_ih, W_hh, gb, un, k0 + 1));
            A[mt][kt][2] = packh2(sa * wval(W_ih, W_hh, ga, un, k0 + 8),
                                  sa * wval(W_ih, W_hh, ga, un, k0 + 9));
            A[mt][kt][3] = packh2(sb * wval(W_ih, W_hh, gb, un, k0 + 8),
                                  sb * wval(W_ih, W_hh, gb, un, k0 + 9));
        }
    }

    // ---- x staging (224 threads): batch lb (0..27), features iv..iv+3 ----
    const int lb  = tid >> 3;
    const int iv  = (tid & 7) * 4;
    const bool xth  = (tid < 224);
    const bool bval = xth && (bbase + lb) < Btotal;
    const float* xrow = x + (bval ? (size_t)(bbase + lb) * TT * 32 : 0) + iv;

    float4 xr;
    if (xth) {
        float4 x0 = *(const float4*)xrow;
        stw[lb * PW + (iv >> 1)]     = packh2(x0.x, x0.y);      // buf 0
        stw[lb * PW + (iv >> 1) + 1] = packh2(x0.z, x0.w);
        xr = *(const float4*)(xrow + 32);
    }
    __syncthreads();

    // ---- anti-phase skew: second resident CTA on each SM delays half a step ----
    if (blockIdx.x >= 148) {
        unsigned long long t0 = clock64();
        while (clock64() - t0 < SKEW_CYC) { }
    }

    const float4 bz = *(const float4*)&bias[un * 4];
    float cst[8];
#pragma unroll
    for (int i = 0; i < 8; ++i) cst[i] = 0.0f;

    int p = 0;
    for (int t = 0; t < TT; ++t) {
        const uint32_t* sb = stw + p * STB;
        const int q = 1 - p;

        // ===== GEMM: all 4 gates of unit `un`, 8 batches, from buf p =====
        float D0[4][4], D1[4][4];
#pragma unroll
        for (int ntp = 0; ntp < 4; ++ntp) {
            const int n0 = 8 * ntp;
            const uint32_t* s0 = sb + (n0 + fr) * PW + fc;
#pragma unroll
            for (int e = 0; e < 4; ++e) { D0[ntp][e] = 0.f; D1[ntp][e] = 0.f; }
#pragma unroll
            for (int kt = 0; kt < 6; ++kt) {
                uint32_t b0 = s0[kt * 8];
                uint32_t b1 = s0[kt * 8 + 4];
                mma16(D0[ntp], A[0][kt], b0, b1);
                mma16(D1[ntp], A[1][kt], b0, b1);
            }
        }

        // stage x(t+1) into buf q early (independent of activations)
        if (xth && t + 1 < TT) {
            stw[q * STB + lb * PW + (iv >> 1)]     = packh2(xr.x, xr.y);
            stw[q * STB + lb * PW + (iv >> 1) + 1] = packh2(xr.z, xr.w);
            int tn = (t + 2 < TT) ? (t + 2) : (TT - 1);
            xr = *(const float4*)(xrow + (size_t)tn * 32);
        }

        // ===== activations straight from fragments; h -> buf q =====
        const bool lastt = (t == TT - 1);
#pragma unroll
        for (int ntp = 0; ntp < 4; ++ntp) {
#pragma unroll
            for (int e = 0; e < 2; ++e) {
                const int b = 8 * ntp + 2 * fc + e;
                float gi = fsigp(D0[ntp][e]     + bz.x);
                float gf = fsigp(D0[ntp][2 + e] + bz.y);
                float gg = tanha(D1[ntp][e]     + bz.z);
                float go = fsigp(D1[ntp][2 + e] + bz.w);
                const int ci = 2 * ntp + e;
                float cn = fmaf(gf, cst[ci], gi * gg);
                cst[ci] = cn;
                float h = go * tanha(cn);
                if (lastt) hfin[b * PH + un] = h;
                else       sth[q * (2 * STB) + b * (2 * PW) + 32 + un] = __float2half_rn(h);
            }
        }

        __syncthreads();
        p = q;
    }

    // ---- final FC on raw f32 h(T) ----
    if (xth) {
        const int ob = tid >> 3, oo = tid & 7;
        if ((bbase + ob) < Btotal) {
            const float* hv = hfin + ob * PH;
            float a = b_fc[oo];
#pragma unroll 8
            for (int k = 0; k < 64; ++k)
                a = fmaf(hv[k], W_fc[oo * 64 + k], a);
            out[(size_t)(bbase + ob) * 8 + oo] = a;
        }
    }
}

extern "C" void kernel_launch(void* const* d_in, const int* in_sizes, int n_in,
                              void* d_out, int out_size) {
    const float* x    = (const float*)d_in[0];
    const float* W_ih = (const float*)d_in[1];
    const float* W_hh = (const float*)d_in[2];
    const float* b_ih = (const float*)d_in[3];
    const float* b_hh = (const float*)d_in[4];
    const float* W_fc = (const float*)d_in[5];
    const float* b_fc = (const float*)d_in[6];
    float* out = (float*)d_out;

    const int B = in_sizes[0] / (TT * 32);    // 8192
    const int grid = (B + BM - 1) / BM;       // 293

    cudaFuncSetAttribute(lstm_mma,
                         cudaFuncAttributeMaxDynamicSharedMemorySize,
                         SMEM_BYTES);
    lstm_mma<<<grid, NTHR, SMEM_BYTES>>>(x, W_ih, W_hh, b_ih, b_hh,
                                         W_fc, b_fc, out, B);
}